// round 12
// baseline (speedup 1.0000x reference)
#include <cuda_runtime.h>
#include <cstdint>

typedef unsigned long long u64;

#define KOUT    512
#define BMAX    512
#define CAP     2048
#define NB      4096
#define SLICES  8
#define NT1     256
#define NT2     512

__device__ u64      g_buf[BMAX * CAP];   // candidate scratch (8 MB)
__device__ unsigned g_cnt[BMAX];         // zero-initialized; sort kernel re-zeroes

__device__ __forceinline__ unsigned fkey(float f) {
    unsigned u = __float_as_uint(f);
    return u ^ ((u & 0x80000000u) ? 0xFFFFFFFFu : 0x80000000u);
}
__device__ __forceinline__ float finv(unsigned v) {
    unsigned u = v ^ ((v & 0x80000000u) ? 0x80000000u : 0xFFFFFFFFu);
    return __uint_as_float(u);
}
__device__ __forceinline__ u64 pack(float x, float y) {
    return ((u64)fkey(x) << 32) | (u64)fkey(y);
}

// lower-tail probit (Hastings), valid for 0 < q < 0.5, |err| < 4.5e-4
__device__ __forceinline__ float probit_lo(float q) {
    float t = sqrtf(-2.0f * logf(q));
    float num = 2.515517f + t * (0.802853f + t * 0.010328f);
    float den = 1.0f + t * (1.432788f + t * (0.189269f + t * 0.001308f));
    return -(t - num / den);
}

template <int NTH>
__device__ void find_pivot(int* hist, int target, int* wsum,
                           int* s_pivot, int* s_below) {
    const int t = threadIdx.x;
    const int BPT = NB / NTH;
    const int base = t * BPT;
    int local = 0;
#pragma unroll
    for (int j = 0; j < BPT; j++) local += hist[base + j];
    const int lane = t & 31, warp = t >> 5;
    int incl = local;
#pragma unroll
    for (int o = 1; o < 32; o <<= 1) {
        int v = __shfl_up_sync(0xFFFFFFFFu, incl, o);
        if (lane >= o) incl += v;
    }
    if (lane == 31) wsum[warp] = incl;
    __syncthreads();
    if (t == 0) {
        int acc = 0;
#pragma unroll
        for (int i = 0; i < NTH / 32; i++) { int v = wsum[i]; wsum[i] = acc; acc += v; }
    }
    __syncthreads();
    const int excl = wsum[warp] + incl - local;
    if (excl < target && excl + local >= target) {
        int c = excl;
#pragma unroll
        for (int j = 0; j < BPT; j++) {
            int h = hist[base + j];
            if (c + h >= target) { *s_pivot = base + j; *s_below = c; break; }
            c += h;
        }
    }
    __syncthreads();
}

// ================= kernel 1: sliced filtered scan (analytic threshold) =================
__global__ __launch_bounds__(NT1)
void scan_kernel(const float2* __restrict__ corners,
                 const int* __restrict__ lengths, int M) {
    const int b = blockIdx.y, s = blockIdx.x, t = threadIdx.x;
    const int n = lengths[b];
    if (n == 0) return;

    float hi;
    if (n <= CAP) {
        hi = __int_as_float(0x7F800000);   // +inf: keep everything
    } else {
        const int kk = n < KOUT ? n : KOUT;
        float q = 1.55f * (float)kk / (float)n + 64.0f / (float)n;  // < 0.42
        hi = probit_lo(q);
    }

    int n8 = ((n + SLICES - 1) / SLICES + 1) & ~1;   // even slice size (float4 aligned)
    int lo = s * n8;
    int end = lo + n8 < n ? lo + n8 : n;
    if (lo >= end) return;
    const float2* base = corners + (size_t)b * M;
    u64* gb = g_buf + (size_t)b * CAP;
    unsigned* gc = &g_cnt[b];

    int i = lo + 2 * t;
    for (; i + 2 * NT1 + 1 < end; i += 4 * NT1) {
        float4 a = *(const float4*)(base + i);
        float4 c = *(const float4*)(base + i + 2 * NT1);
        if (a.x <= hi) { unsigned p = atomicAdd(gc, 1u); if (p < CAP) gb[p] = pack(a.x, a.y); }
        if (a.z <= hi) { unsigned p = atomicAdd(gc, 1u); if (p < CAP) gb[p] = pack(a.z, a.w); }
        if (c.x <= hi) { unsigned p = atomicAdd(gc, 1u); if (p < CAP) gb[p] = pack(c.x, c.y); }
        if (c.z <= hi) { unsigned p = atomicAdd(gc, 1u); if (p < CAP) gb[p] = pack(c.z, c.w); }
    }
    for (; i + 1 < end; i += 2 * NT1) {
        float4 a = *(const float4*)(base + i);
        if (a.x <= hi) { unsigned p = atomicAdd(gc, 1u); if (p < CAP) gb[p] = pack(a.x, a.y); }
        if (a.z <= hi) { unsigned p = atomicAdd(gc, 1u); if (p < CAP) gb[p] = pack(a.z, a.w); }
    }
    if (i < end) {
        float2 c = base[i];
        if (c.x <= hi) { unsigned p = atomicAdd(gc, 1u); if (p < CAP) gb[p] = pack(c.x, c.y); }
    }
}

// ================= kernel 2: exact-512 select + sort + emit =================
struct Sh2 {
    u64 buf[CAP];
    union { int hist[NB]; u64 buf2[CAP]; };
    int wsum[NT2 / 32];
    u64 mnw[NT2 / 32], mxw[NT2 / 32];
    u64 s_mn, s_mx;
    int cnt, cnt2, pivot, below;
};

__device__ void bitonic(u64* a, int P) {
    const int t = threadIdx.x;
    for (int size = 2; size <= P; size <<= 1)
        for (int stride = size >> 1; stride > 0; stride >>= 1) {
            for (int i = t; i < P; i += NT2) {
                int j = i ^ stride;
                if (j > i) {
                    u64 x = a[i], y = a[j];
                    bool up = ((i & size) == 0);
                    if ((x > y) == up) { a[i] = y; a[j] = x; }
                }
            }
            __syncthreads();
        }
}

__global__ __launch_bounds__(NT2)
void sort_kernel(const float2* __restrict__ corners,
                 const int* __restrict__ lengths,
                 float2* __restrict__ out, int M) {
    __shared__ Sh2 sh;
    const int b = blockIdx.x, t = threadIdx.x;
    const int n = lengths[b];
    const int kk = n < KOUT ? n : KOUT;
    float2* outp = out + (size_t)b * KOUT;
    if (kk == 0) { outp[t] = make_float2(0.f, 0.f); return; }
    const float2* base = corners + (size_t)b * M;

    unsigned rawc = g_cnt[b];
    __syncthreads();
    if (t == 0) g_cnt[b] = 0;        // reset for next graph replay

    int C;
    if (rawc >= (unsigned)kk && rawc <= CAP) {
        C = (int)rawc;
        for (int i = t; i < C; i += NT2) sh.buf[i] = g_buf[(size_t)b * CAP + i];
        __syncthreads();
    } else {
        // exact fallback: 3-level histogram on x over full batch (rare)
        for (int i = t; i < NB; i += NT2) sh.hist[i] = 0;
        __syncthreads();
        for (int i = t; i < n; i += NT2) atomicAdd(&sh.hist[fkey(base[i].x) >> 20], 1);
        __syncthreads();
        find_pivot<NT2>(sh.hist, kk, sh.wsum, &sh.pivot, &sh.below);
        int d0 = sh.pivot, below0 = sh.below, in0 = sh.hist[d0];
        unsigned T;
        if (below0 + in0 <= CAP) T = ((unsigned)d0 << 20) | 0xFFFFFu;
        else {
            __syncthreads();
            for (int i = t; i < NB; i += NT2) sh.hist[i] = 0;
            __syncthreads();
            for (int i = t; i < n; i += NT2) {
                unsigned u = fkey(base[i].x);
                if ((u >> 20) == (unsigned)d0) atomicAdd(&sh.hist[(u >> 8) & 0xFFFu], 1);
            }
            __syncthreads();
            find_pivot<NT2>(sh.hist, kk - below0, sh.wsum, &sh.pivot, &sh.below);
            int d1 = sh.pivot, below1 = sh.below, in1 = sh.hist[d1];
            if (below0 + below1 + in1 <= CAP)
                T = ((unsigned)d0 << 20) | ((unsigned)d1 << 8) | 0xFFu;
            else {
                __syncthreads();
                for (int i = t; i < NB; i += NT2) sh.hist[i] = 0;
                __syncthreads();
                const unsigned pref = ((unsigned)d0 << 12) | (unsigned)d1;
                for (int i = t; i < n; i += NT2) {
                    unsigned u = fkey(base[i].x);
                    if ((u >> 8) == pref) atomicAdd(&sh.hist[u & 0xFFu], 1);
                }
                __syncthreads();
                find_pivot<NT2>(sh.hist, kk - below0 - below1, sh.wsum, &sh.pivot, &sh.below);
                T = ((unsigned)d0 << 20) | ((unsigned)d1 << 8) | (unsigned)sh.pivot;
            }
        }
        if (t == 0) sh.cnt = 0;
        __syncthreads();
        for (int i = t; i < n; i += NT2) {
            float2 c = base[i];
            if (fkey(c.x) <= T) {
                int pos = atomicAdd(&sh.cnt, 1);
                if (pos < CAP) sh.buf[pos] = pack(c.x, c.y);
            }
        }
        __syncthreads();
        C = sh.cnt < CAP ? sh.cnt : CAP;
    }

    u64* sbuf = sh.buf;
    // ---- adaptive-range selection to exactly kk elements ----
    if (C > kk) {
        u64 mn = ~0ull, mx = 0ull;
        for (int i = t; i < C; i += NT2) {
            u64 k = sh.buf[i];
            mn = k < mn ? k : mn;
            mx = k > mx ? k : mx;
        }
        const int lane = t & 31, warp = t >> 5;
#pragma unroll
        for (int o = 16; o > 0; o >>= 1) {
            u64 a = __shfl_down_sync(0xFFFFFFFFu, mn, o);
            u64 bx = __shfl_down_sync(0xFFFFFFFFu, mx, o);
            mn = a < mn ? a : mn;
            mx = bx > mx ? bx : mx;
        }
        if (lane == 0) { sh.mnw[warp] = mn; sh.mxw[warp] = mx; }
        __syncthreads();
        if (t == 0) {
            u64 m0 = ~0ull, m1 = 0ull;
            for (int i = 0; i < NT2 / 32; i++) {
                m0 = sh.mnw[i] < m0 ? sh.mnw[i] : m0;
                m1 = sh.mxw[i] > m1 ? sh.mxw[i] : m1;
            }
            sh.s_mn = m0; sh.s_mx = m1;
        }
        __syncthreads();
        const u64 kmn = sh.s_mn, kmx = sh.s_mx;
        if (kmn == kmx) {
            C = kk;                    // all keys identical
        } else {
            u64 range = kmx - kmn;
            int hb = 63 - __clzll(range);
            int shift = hb - 11; if (shift < 0) shift = 0;
            for (int i = t; i < NB; i += NT2) sh.hist[i] = 0;
            __syncthreads();
            for (int i = t; i < C; i += NT2)
                atomicAdd(&sh.hist[(int)((sh.buf[i] - kmn) >> shift)], 1);
            __syncthreads();
            find_pivot<NT2>(sh.hist, kk, sh.wsum, &sh.pivot, &sh.below);
            const int p = sh.pivot, below = sh.below;
            const int m = sh.hist[p];
            __syncthreads();           // hist reads done; buf2 aliases hist
            if (t == 0) { sh.cnt = 0; sh.cnt2 = 0; }
            __syncthreads();
            // partition: bin<p -> buf2[0..below), bin==p -> buf2[1024..1024+m)
            for (int i = t; i < C; i += NT2) {
                u64 k = sh.buf[i];
                int bin = (int)((k - kmn) >> shift);
                if (bin < p) {
                    int pos = atomicAdd(&sh.cnt, 1);
                    sh.buf2[pos] = k;
                } else if (bin == p) {
                    int pos = atomicAdd(&sh.cnt2, 1);
                    if (pos < 1024) sh.buf2[1024 + pos] = k;
                }
            }
            __syncthreads();
            if (m <= 1024) {
                // mini-sort the pivot bin, take exactly (kk - below) smallest
                int P2 = 1; while (P2 < m) P2 <<= 1;
                if (P2 < 2) P2 = 2;
                for (int i = m + t; i < P2; i += NT2) sh.buf2[1024 + i] = ~0ull;
                __syncthreads();
                bitonic(sh.buf2 + 1024, P2);
                const int need = kk - below;
                for (int i = t; i < need; i += NT2)
                    sh.buf2[below + i] = sh.buf2[1024 + i];
                __syncthreads();
                C = kk;
                sbuf = sh.buf2;
            }
            // else pathological: sort full buf (C <= CAP)
        }
    }

    int P = 1; while (P < C) P <<= 1;
    if (P < 2) P = 2;
    for (int i = C + t; i < P; i += NT2) sbuf[i] = ~0ull;
    __syncthreads();
    bitonic(sbuf, P);

    float2 o = make_float2(0.f, 0.f);
    if (t < kk) {
        u64 k = sbuf[t];
        o = make_float2(finv((unsigned)(k >> 32)), finv((unsigned)k));
    }
    outp[t] = o;
}

extern "C" void kernel_launch(void* const* d_in, const int* in_sizes, int n_in,
                              void* d_out, int out_size) {
    const float2* corners = (const float2*)d_in[0];
    const int*    lengths = (const int*)d_in[1];
    float2*       out     = (float2*)d_out;
    const int B = in_sizes[1];
    const int M = in_sizes[0] / (B * 2);
    scan_kernel<<<dim3(SLICES, B), NT1>>>(corners, lengths, M);
    sort_kernel<<<B, NT2>>>(corners, lengths, out, M);
}

// round 13
// speedup vs baseline: 2.4041x; 2.4041x over previous
#include <cuda_runtime.h>
#include <cstdint>

typedef unsigned long long u64;

#define KOUT 512
#define NT   512
#define CAP  2048
#define NB   4096
#define BPT  (NB / NT)    // 8

__device__ __forceinline__ unsigned fkey(float f) {
    unsigned u = __float_as_uint(f);
    return u ^ ((u & 0x80000000u) ? 0xFFFFFFFFu : 0x80000000u);
}
__device__ __forceinline__ float finv(unsigned v) {
    unsigned u = v ^ ((v & 0x80000000u) ? 0x80000000u : 0xFFFFFFFFu);
    return __uint_as_float(u);
}
__device__ __forceinline__ u64 pack(float x, float y) {
    return ((u64)fkey(x) << 32) | (u64)fkey(y);
}

// lower-tail probit (Hastings), valid for 0 < q < 0.5, |err| < 4.5e-4
__device__ __forceinline__ float probit_lo(float q) {
    float t = sqrtf(-2.0f * logf(q));
    float num = 2.515517f + t * (0.802853f + t * 0.010328f);
    float den = 1.0f + t * (1.432788f + t * (0.189269f + t * 0.001308f));
    return -(t - num / den);
}

struct Sh {
    u64 buf[CAP];                              // 16 KB candidates
    union { int hist[NB]; u64 buf2[CAP]; };    // 16 KB hist / staging
    int wsum[NT / 32];
    u64 mnw[NT / 32], mxw[NT / 32];
    u64 s_mn, s_mx;
    int cnt, cnt2, pivot, below;
};

__device__ void find_pivot(Sh& sh, int target) {
    const int t = threadIdx.x;
    const int base = t * BPT;
    int local = 0;
#pragma unroll
    for (int j = 0; j < BPT; j++) local += sh.hist[base + j];
    const int lane = t & 31, warp = t >> 5;
    int incl = local;
#pragma unroll
    for (int o = 1; o < 32; o <<= 1) {
        int v = __shfl_up_sync(0xFFFFFFFFu, incl, o);
        if (lane >= o) incl += v;
    }
    if (lane == 31) sh.wsum[warp] = incl;
    __syncthreads();
    if (t == 0) {
        int acc = 0;
#pragma unroll
        for (int i = 0; i < NT / 32; i++) { int v = sh.wsum[i]; sh.wsum[i] = acc; acc += v; }
    }
    __syncthreads();
    const int excl = sh.wsum[warp] + incl - local;
    if (excl < target && excl + local >= target) {
        int c = excl;
#pragma unroll
        for (int j = 0; j < BPT; j++) {
            int h = sh.hist[base + j];
            if (c + h >= target) { sh.pivot = base + j; sh.below = c; break; }
            c += h;
        }
    }
    __syncthreads();
}

__device__ void bitonic(u64* a, int P) {
    const int t = threadIdx.x;
    for (int size = 2; size <= P; size <<= 1)
        for (int stride = size >> 1; stride > 0; stride >>= 1) {
            for (int i = t; i < P; i += NT) {
                int j = i ^ stride;
                if (j > i) {
                    u64 x = a[i], y = a[j];
                    bool up = ((i & size) == 0);
                    if ((x > y) == up) { a[i] = y; a[j] = x; }
                }
            }
            __syncthreads();
        }
}

__device__ __forceinline__ void push(Sh& sh, u64 k) {
    int pos = atomicAdd(&sh.cnt, 1);
    if (pos < CAP) sh.buf[pos] = k;
}

__global__ __launch_bounds__(NT, 4)
void topk_fused(const float2* __restrict__ corners,
                const int*    __restrict__ lengths,
                float2*       __restrict__ out, int M) {
    __shared__ Sh sh;
    const int b = blockIdx.x, t = threadIdx.x;
    const int n = lengths[b];
    const int kk = n < KOUT ? n : KOUT;
    float2* outp = out + (size_t)b * KOUT;
    if (kk == 0) { outp[t] = make_float2(0.f, 0.f); return; }
    const float2* base = corners + (size_t)b * M;

    // ---- analytic x-threshold (statistical; exact fallback guards it) ----
    float hi;
    if (n <= CAP) {
        hi = __int_as_float(0x7F800000);                       // keep all
    } else {
        float q = 1.55f * (float)kk / (float)n + 64.0f / (float)n;  // < 0.42
        hi = probit_lo(q);
    }

    if (t == 0) sh.cnt = 0;
    __syncthreads();

    // ---- gather: single filtered pass, 2 LDG.128 in flight per thread ----
    {
        int i = 2 * t;
        for (; i + 2 * NT + 1 < n; i += 4 * NT) {
            float4 a = *(const float4*)(base + i);
            float4 c = *(const float4*)(base + i + 2 * NT);
            if (a.x <= hi) push(sh, pack(a.x, a.y));
            if (a.z <= hi) push(sh, pack(a.z, a.w));
            if (c.x <= hi) push(sh, pack(c.x, c.y));
            if (c.z <= hi) push(sh, pack(c.z, c.w));
        }
        for (; i + 1 < n; i += 2 * NT) {
            float4 a = *(const float4*)(base + i);
            if (a.x <= hi) push(sh, pack(a.x, a.y));
            if (a.z <= hi) push(sh, pack(a.z, a.w));
        }
        if (i < n) {
            float2 c = base[i];
            if (c.x <= hi) push(sh, pack(c.x, c.y));
        }
    }
    __syncthreads();

    int rawc = sh.cnt;
    int C;
    if (rawc >= kk && rawc <= CAP) {
        C = rawc;
    } else {
        // ---- exact fallback: 3-level histogram refinement on x (rare) ----
        for (int i = t; i < NB; i += NT) sh.hist[i] = 0;
        __syncthreads();
        for (int i = t; i < n; i += NT) atomicAdd(&sh.hist[fkey(base[i].x) >> 20], 1);
        __syncthreads();
        find_pivot(sh, kk);
        int d0 = sh.pivot, below0 = sh.below, in0 = sh.hist[d0];
        unsigned T;
        if (below0 + in0 <= CAP) T = ((unsigned)d0 << 20) | 0xFFFFFu;
        else {
            __syncthreads();
            for (int i = t; i < NB; i += NT) sh.hist[i] = 0;
            __syncthreads();
            for (int i = t; i < n; i += NT) {
                unsigned u = fkey(base[i].x);
                if ((u >> 20) == (unsigned)d0) atomicAdd(&sh.hist[(u >> 8) & 0xFFFu], 1);
            }
            __syncthreads();
            find_pivot(sh, kk - below0);
            int d1 = sh.pivot, below1 = sh.below, in1 = sh.hist[d1];
            if (below0 + below1 + in1 <= CAP)
                T = ((unsigned)d0 << 20) | ((unsigned)d1 << 8) | 0xFFu;
            else {
                __syncthreads();
                for (int i = t; i < NB; i += NT) sh.hist[i] = 0;
                __syncthreads();
                const unsigned pref = ((unsigned)d0 << 12) | (unsigned)d1;
                for (int i = t; i < n; i += NT) {
                    unsigned u = fkey(base[i].x);
                    if ((u >> 8) == pref) atomicAdd(&sh.hist[u & 0xFFu], 1);
                }
                __syncthreads();
                find_pivot(sh, kk - below0 - below1);
                T = ((unsigned)d0 << 20) | ((unsigned)d1 << 8) | (unsigned)sh.pivot;
            }
        }
        if (t == 0) sh.cnt = 0;
        __syncthreads();
        for (int i = t; i < n; i += NT) {
            float2 c = base[i];
            if (fkey(c.x) <= T) push(sh, pack(c.x, c.y));
        }
        __syncthreads();
        C = sh.cnt < CAP ? sh.cnt : CAP;
    }

    u64* sbuf = sh.buf;
    // ---- adaptive-range selection to exactly kk elements ----
    if (C > kk) {
        u64 mn = ~0ull, mx = 0ull;
        for (int i = t; i < C; i += NT) {
            u64 k = sh.buf[i];
            mn = k < mn ? k : mn;
            mx = k > mx ? k : mx;
        }
        const int lane = t & 31, warp = t >> 5;
#pragma unroll
        for (int o = 16; o > 0; o >>= 1) {
            u64 a = __shfl_down_sync(0xFFFFFFFFu, mn, o);
            u64 bx = __shfl_down_sync(0xFFFFFFFFu, mx, o);
            mn = a < mn ? a : mn;
            mx = bx > mx ? bx : mx;
        }
        if (lane == 0) { sh.mnw[warp] = mn; sh.mxw[warp] = mx; }
        __syncthreads();
        if (t == 0) {
            u64 m0 = ~0ull, m1 = 0ull;
            for (int i = 0; i < NT / 32; i++) {
                m0 = sh.mnw[i] < m0 ? sh.mnw[i] : m0;
                m1 = sh.mxw[i] > m1 ? sh.mxw[i] : m1;
            }
            sh.s_mn = m0; sh.s_mx = m1;
        }
        __syncthreads();
        const u64 kmn = sh.s_mn, kmx = sh.s_mx;
        if (kmn == kmx) {
            C = kk;                                 // all keys identical
        } else {
            u64 range = kmx - kmn;
            int hb = 63 - __clzll(range);
            int shift = hb - 11; if (shift < 0) shift = 0;
            for (int i = t; i < NB; i += NT) sh.hist[i] = 0;
            __syncthreads();
            for (int i = t; i < C; i += NT)
                atomicAdd(&sh.hist[(int)((sh.buf[i] - kmn) >> shift)], 1);
            __syncthreads();
            find_pivot(sh, kk);
            const int p = sh.pivot, below = sh.below;
            const int m = sh.hist[p];
            __syncthreads();                        // hist reads done (buf2 aliases)
            if (t == 0) { sh.cnt = 0; sh.cnt2 = 0; }
            __syncthreads();
            for (int i = t; i < C; i += NT) {
                u64 k = sh.buf[i];
                int bin = (int)((k - kmn) >> shift);
                if (bin < p) {
                    int pos = atomicAdd(&sh.cnt, 1);
                    sh.buf2[pos] = k;
                } else if (bin == p) {
                    int pos = atomicAdd(&sh.cnt2, 1);
                    if (pos < 1024) sh.buf2[1024 + pos] = k;
                }
            }
            __syncthreads();
            if (m <= 1024) {
                int P2 = 1; while (P2 < m) P2 <<= 1;
                if (P2 < 2) P2 = 2;
                for (int i = m + t; i < P2; i += NT) sh.buf2[1024 + i] = ~0ull;
                __syncthreads();
                bitonic(sh.buf2 + 1024, P2);
                const int need = kk - below;
                for (int i = t; i < need; i += NT)
                    sh.buf2[below + i] = sh.buf2[1024 + i];
                __syncthreads();
                C = kk;
                sbuf = sh.buf2;
            }
            // else pathological: sort full buf (C <= CAP)
        }
    }

    int P = 1; while (P < C) P <<= 1;
    if (P < 2) P = 2;
    for (int i = C + t; i < P; i += NT) sbuf[i] = ~0ull;
    __syncthreads();
    bitonic(sbuf, P);

    float2 o = make_float2(0.f, 0.f);
    if (t < kk) {
        u64 k = sbuf[t];
        o = make_float2(finv((unsigned)(k >> 32)), finv((unsigned)k));
    }
    outp[t] = o;
}

extern "C" void kernel_launch(void* const* d_in, const int* in_sizes, int n_in,
                              void* d_out, int out_size) {
    const float2* corners = (const float2*)d_in[0];
    const int*    lengths = (const int*)d_in[1];
    float2*       out     = (float2*)d_out;
    const int B = in_sizes[1];
    const int M = in_sizes[0] / (B * 2);
    topk_fused<<<B, NT>>>(corners, lengths, out, M);
}